// round 1
// baseline (speedup 1.0000x reference)
#include <cuda_runtime.h>
#include <cuda_bf16.h>
#include <cstdint>

// Problem constants
#define NB      32          // batches
#define NRINGS  10
#define NANG    36
#define NPTS    (NRINGS * NANG)   // 360 points per batch
#define NTGT    16384       // targets per batch
#define NCHUNK  16          // target chunks per batch
#define TC      (NTGT / NCHUNK)   // 1024 targets per chunk
#define THREADS 384

// Scratch: per-(batch,point) running min, stored as monotone-encoded uint keys.
__device__ unsigned int g_keys[NB * NPTS];

// Monotone float -> uint encoding (total order matches float order incl. negatives)
__device__ __forceinline__ unsigned int enc_f32(float f) {
    unsigned int u = __float_as_uint(f);
    return (u & 0x80000000u) ? ~u : (u | 0x80000000u);
}
__device__ __forceinline__ float dec_f32(unsigned int k) {
    unsigned int u = (k & 0x80000000u) ? (k ^ 0x80000000u) : ~k;
    return __uint_as_float(u);
}

__global__ void init_keys_kernel() {
    int i = blockIdx.x * blockDim.x + threadIdx.x;
    if (i < NB * NPTS) g_keys[i] = 0xFFFFFFFFu;   // max key
}

// Main kernel: block = (chunk c, batch b). Each of the 360 active threads owns one
// generated point and scans TC targets staged in shared memory (broadcast LDS.128).
// Inner loop per target: v = t2 + qx*tx + qy*ty + qz*tz  (3 FFMA) ; m = min(m, v) (FMNMX).
__global__ void __launch_bounds__(THREADS)
chamfer_min_kernel(const float* __restrict__ pred,
                   const float* __restrict__ target) {
    __shared__ float4 sm[TC];

    const int chunk = blockIdx.x;
    const int b     = blockIdx.y;
    const int tid   = threadIdx.x;

    // Stage target chunk: (tx, ty, tz, t2)
    const float* tg = target + ((size_t)b * NTGT + (size_t)chunk * TC) * 3;
    for (int i = tid; i < TC; i += THREADS) {
        float tx = tg[i * 3 + 0];
        float ty = tg[i * 3 + 1];
        float tz = tg[i * 3 + 2];
        float t2 = tx * tx + ty * ty + tz * tz;
        sm[i] = make_float4(tx, ty, tz, t2);
    }
    __syncthreads();

    // Per-thread point generation (matches reference numerics in f32)
    const int  p      = tid;
    const bool active = (p < NPTS);
    const int  j      = p / NANG;
    const int  a      = p - j * NANG;

    float r = 0.0f;
    if (active) r = pred[b * NRINGS + j];

    const float k   = (float)(2.0 * 3.1415926 / 360.0);
    const float ang = (float)(10 * a) * k;
    float c, s;
    __sincosf(ang, &s, &c);           // fast path; refine below for accuracy
    // Use accurate sin/cos (reference uses full-precision f32 cos/sin)
    c = cosf(ang);
    s = sinf(ang);

    const float px = -r * c + 0.04f;
    const float py = 0.15f * (float)j - 0.7f;
    const float pz = r * s;
    const float p2 = px * px + py * py + pz * pz;

    const float qx = -2.0f * px;
    const float qy = -2.0f * py;
    const float qz = -2.0f * pz;

    const float INF = __int_as_float(0x7f800000);
    float m0 = INF, m1 = INF, m2 = INF, m3 = INF;

    #pragma unroll 4
    for (int n = 0; n < TC; n += 4) {
        float4 t0 = sm[n + 0];
        float4 t1 = sm[n + 1];
        float4 t2 = sm[n + 2];
        float4 t3 = sm[n + 3];
        float v0 = fmaf(qx, t0.x, fmaf(qy, t0.y, fmaf(qz, t0.z, t0.w)));
        float v1 = fmaf(qx, t1.x, fmaf(qy, t1.y, fmaf(qz, t1.z, t1.w)));
        float v2 = fmaf(qx, t2.x, fmaf(qy, t2.y, fmaf(qz, t2.z, t2.w)));
        float v3 = fmaf(qx, t3.x, fmaf(qy, t3.y, fmaf(qz, t3.z, t3.w)));
        m0 = fminf(m0, v0);
        m1 = fminf(m1, v1);
        m2 = fminf(m2, v2);
        m3 = fminf(m3, v3);
    }
    float m = fminf(fminf(m0, m1), fminf(m2, m3));

    if (active) {
        float d2c = p2 + m;               // chunk-local min of (d2 before clamp)
        atomicMin(&g_keys[b * NPTS + p], enc_f32(d2c));
    }
}

// Deterministic single-block mean reduce: decode keys, clamp >= 0, mean over 11520.
__global__ void __launch_bounds__(1024)
reduce_mean_kernel(float* __restrict__ out) {
    __shared__ float wsum[32];
    const int tid = threadIdx.x;

    float s = 0.0f;
    for (int i = tid; i < NB * NPTS; i += 1024) {
        float f = dec_f32(g_keys[i]);
        s += fmaxf(f, 0.0f);
    }
    #pragma unroll
    for (int o = 16; o > 0; o >>= 1) s += __shfl_down_sync(0xffffffffu, s, o);
    if ((tid & 31) == 0) wsum[tid >> 5] = s;
    __syncthreads();
    if (tid < 32) {
        float v = wsum[tid];
        #pragma unroll
        for (int o = 16; o > 0; o >>= 1) v += __shfl_down_sync(0xffffffffu, v, o);
        if (tid == 0) out[0] = v / (float)(NB * NPTS);
    }
}

extern "C" void kernel_launch(void* const* d_in, const int* in_sizes, int n_in,
                              void* d_out, int out_size) {
    const float* pred   = (const float*)d_in[0];   // (32, 10)
    const float* target = (const float*)d_in[1];   // (32, 16384, 3)
    // d_in[2] = trans_feat : unused by reference
    float* out = (float*)d_out;

    init_keys_kernel<<<(NB * NPTS + 1023) / 1024, 1024>>>();

    dim3 grid(NCHUNK, NB);
    chamfer_min_kernel<<<grid, THREADS>>>(pred, target);

    reduce_mean_kernel<<<1, 1024>>>(out);
}

// round 2
// speedup vs baseline: 1.6185x; 1.6185x over previous
#include <cuda_runtime.h>
#include <cuda_bf16.h>
#include <cstdint>

// Problem constants
#define NB      32
#define NRINGS  10
#define NANG    36
#define NPTS    (NRINGS * NANG)     // 360
#define NTGT    16384
#define NCHUNK  16
#define TC      (NTGT / NCHUNK)     // 1024 targets per chunk
#define TPB     (NRINGS * 32)       // 320 threads: warp = ring, lanes = targets

// Per-(batch,point,chunk) partial minima. Fully rewritten every launch.
__device__ float g_part[NB * NPTS * NCHUNK];

// cos/sin of a*10 degrees (reference PI_APPROX shifts angles by <3e-8 rad -> negligible)
__device__ static const float CS_TAB[NANG] = {
    1.0f,                  0.9848077530122080f,  0.9396926207859084f,  0.8660254037844387f,
    0.7660444431189780f,   0.6427876096865393f,  0.5f,                 0.3420201433256688f,
    0.1736481776669304f,   0.0f,                -0.1736481776669303f, -0.3420201433256687f,
   -0.5f,                 -0.6427876096865393f, -0.7660444431189780f, -0.8660254037844387f,
   -0.9396926207859083f,  -0.9848077530122080f, -1.0f,                -0.9848077530122081f,
   -0.9396926207859085f,  -0.8660254037844388f, -0.7660444431189783f, -0.6427876096865395f,
   -0.5f,                 -0.3420201433256690f, -0.1736481776669307f,  0.0f,
    0.1736481776669300f,   0.3420201433256682f,  0.5f,                 0.6427876096865389f,
    0.7660444431189780f,   0.8660254037844384f,  0.9396926207859082f,  0.9848077530122080f
};
__device__ static const float SN_TAB[NANG] = {
    0.0f,                  0.1736481776669304f,  0.3420201433256687f,  0.5f,
    0.6427876096865393f,   0.7660444431189780f,  0.8660254037844386f,  0.9396926207859083f,
    0.9848077530122080f,   1.0f,                 0.9848077530122081f,  0.9396926207859084f,
    0.8660254037844387f,   0.7660444431189781f,  0.6427876096865395f,  0.5f,
    0.3420201433256689f,   0.1736481776669306f,  0.0f,                -0.1736481776669303f,
   -0.3420201433256685f,  -0.5f,                -0.6427876096865390f, -0.7660444431189779f,
   -0.8660254037844384f,  -0.9396926207859082f, -0.9848077530122080f, -1.0f,
   -0.9848077530122082f,  -0.9396926207859086f, -0.8660254037844390f, -0.7660444431189783f,
   -0.6427876096865396f,  -0.5f,                -0.3420201433256691f, -0.1736481776669308f
};

// Main kernel. Block = (chunk, batch). Warp w handles ring w, its 32 lanes
// stride the 1024 staged targets. Per (target): 1 LDS.128 + 4 setup ops, then
// 36 x { d2 = fma(C[a],U, fma(S[a],V, A)); m[a]=min(m[a],d2) } with C,S as
// FFMA immediates (rt_SMSP=1 fast path).
__global__ void __launch_bounds__(TPB)
chamfer_min_kernel(const float* __restrict__ pred,
                   const float* __restrict__ target) {
    __shared__ float4 sm[TC];   // (e = 2tx-0.08, ty2 = -2ty, tz2 = -2tz, w = t2-0.08tx)

    const int chunk = blockIdx.x;
    const int b     = blockIdx.y;
    const int tid   = threadIdx.x;

    const float* tg = target + ((size_t)b * NTGT + (size_t)chunk * TC) * 3;
    for (int i = tid; i < TC; i += TPB) {
        float tx = tg[i * 3 + 0];
        float ty = tg[i * 3 + 1];
        float tz = tg[i * 3 + 2];
        float t2 = tx * tx + ty * ty + tz * tz;
        sm[i] = make_float4(2.0f * tx - 0.08f,
                            -2.0f * ty,
                            -2.0f * tz,
                            fmaf(-0.08f, tx, t2));
    }
    __syncthreads();

    const int ring = tid >> 5;
    const int lane = tid & 31;

    const float r  = pred[b * NRINGS + ring];
    const float py = 0.15f * (float)ring - 0.7f;
    const float Kr = r * r + py * py + 0.0016f;

    const float INF = __int_as_float(0x7f800000);
    float m[NANG];
    #pragma unroll
    for (int a = 0; a < NANG; a++) m[a] = INF;

    #pragma unroll 2
    for (int t = lane; t < TC; t += 32) {
        float4 v = sm[t];
        float A = fmaf(py, v.y, v.w) + Kr;
        float U = r * v.x;
        float V = r * v.z;
        #pragma unroll
        for (int a = 0; a < NANG; a++) {
            float d2 = fmaf(CS_TAB[a], U, fmaf(SN_TAB[a], V, A));
            m[a] = fminf(m[a], d2);
        }
    }

    // Reduce each angle across the 32 lanes; write per-chunk partial (no atomics).
    const size_t base = ((size_t)b * NPTS + (size_t)ring * NANG) * NCHUNK + chunk;
    #pragma unroll
    for (int a = 0; a < NANG; a++) {
        float v = m[a];
        #pragma unroll
        for (int o = 16; o > 0; o >>= 1)
            v = fminf(v, __shfl_xor_sync(0xffffffffu, v, o));
        if (lane == (a & 31))
            g_part[base + (size_t)a * NCHUNK] = v;
    }
}

// Deterministic single-block reduce: min over 16 chunks (float4 x4 loads),
// clamp >= 0, mean over 11520 points.
__global__ void __launch_bounds__(1024)
reduce_mean_kernel(float* __restrict__ out) {
    __shared__ float wsum[32];
    const int tid = threadIdx.x;

    float s = 0.0f;
    for (int i = tid; i < NB * NPTS; i += 1024) {
        const float4* q = (const float4*)(g_part + (size_t)i * NCHUNK);
        float4 a = q[0], b4 = q[1], c4 = q[2], d4 = q[3];
        float m0 = fminf(fminf(a.x, a.y), fminf(a.z, a.w));
        float m1 = fminf(fminf(b4.x, b4.y), fminf(b4.z, b4.w));
        float m2 = fminf(fminf(c4.x, c4.y), fminf(c4.z, c4.w));
        float m3 = fminf(fminf(d4.x, d4.y), fminf(d4.z, d4.w));
        float mn = fminf(fminf(m0, m1), fminf(m2, m3));
        s += fmaxf(mn, 0.0f);
    }
    #pragma unroll
    for (int o = 16; o > 0; o >>= 1) s += __shfl_down_sync(0xffffffffu, s, o);
    if ((tid & 31) == 0) wsum[tid >> 5] = s;
    __syncthreads();
    if (tid < 32) {
        float v = wsum[tid];
        #pragma unroll
        for (int o = 16; o > 0; o >>= 1) v += __shfl_down_sync(0xffffffffu, v, o);
        if (tid == 0) out[0] = v / (float)(NB * NPTS);
    }
}

extern "C" void kernel_launch(void* const* d_in, const int* in_sizes, int n_in,
                              void* d_out, int out_size) {
    const float* pred   = (const float*)d_in[0];   // (32, 10)
    const float* target = (const float*)d_in[1];   // (32, 16384, 3)
    float* out = (float*)d_out;

    dim3 grid(NCHUNK, NB);
    chamfer_min_kernel<<<grid, TPB>>>(pred, target);
    reduce_mean_kernel<<<1, 1024>>>(out);
}

// round 3
// speedup vs baseline: 1.9151x; 1.1832x over previous
#include <cuda_runtime.h>
#include <cuda_bf16.h>
#include <cstdint>

// Problem constants
#define NB      32
#define NRINGS  10
#define NANG    36
#define NPTS    (NRINGS * NANG)     // 360
#define NTGT    16384
#define NCHUNK  16
#define TC      (NTGT / NCHUNK)     // 1024 targets per chunk
#define TPB     (NRINGS * 32)       // 320 threads: warp = ring

// Per-(batch,point) running max of enc(-d2). Zero-initialized at module load;
// the reduce kernel resets every entry to 0 after consuming it, so each graph
// replay sees the sentinel state again. enc() maps all floats to [0x007FFFFF,
// 0xFF800000], strictly > 0, so 0 is a valid "-inf" sentinel for max.
__device__ unsigned int g_keys[NB * NPTS];

__device__ __forceinline__ unsigned int enc_f32(float f) {
    unsigned int u = __float_as_uint(f);
    return ((int)u < 0) ? ~u : (u | 0x80000000u);
}
__device__ __forceinline__ float dec_f32(unsigned int k) {
    unsigned int u = ((int)k < 0) ? (k & 0x7FFFFFFFu) : ~k;
    return __uint_as_float(u);
}

// One eval: d2 = A + C*U + S*V with C,S as compile-time literals -> FFMA-imm.
#define STEP(A_IDX, CV, SV) \
    { float d2 = fmaf(CV, U, fmaf(SV, V, Acc)); m[A_IDX] = fminf(m[A_IDX], d2); }

__device__ __forceinline__ void eval36(float* m, float U, float V, float Acc) {
    STEP( 0,  1.0f,            0.0f)
    STEP( 1,  0.9848077530f,   0.1736481777f)
    STEP( 2,  0.9396926208f,   0.3420201433f)
    STEP( 3,  0.8660254038f,   0.5f)
    STEP( 4,  0.7660444431f,   0.6427876097f)
    STEP( 5,  0.6427876097f,   0.7660444431f)
    STEP( 6,  0.5f,            0.8660254038f)
    STEP( 7,  0.3420201433f,   0.9396926208f)
    STEP( 8,  0.1736481777f,   0.9848077530f)
    STEP( 9,  0.0f,            1.0f)
    STEP(10, -0.1736481777f,   0.9848077530f)
    STEP(11, -0.3420201433f,   0.9396926208f)
    STEP(12, -0.5f,            0.8660254038f)
    STEP(13, -0.6427876097f,   0.7660444431f)
    STEP(14, -0.7660444431f,   0.6427876097f)
    STEP(15, -0.8660254038f,   0.5f)
    STEP(16, -0.9396926208f,   0.3420201433f)
    STEP(17, -0.9848077530f,   0.1736481777f)
    STEP(18, -1.0f,            0.0f)
    STEP(19, -0.9848077530f,  -0.1736481777f)
    STEP(20, -0.9396926208f,  -0.3420201433f)
    STEP(21, -0.8660254038f,  -0.5f)
    STEP(22, -0.7660444431f,  -0.6427876097f)
    STEP(23, -0.6427876097f,  -0.7660444431f)
    STEP(24, -0.5f,           -0.8660254038f)
    STEP(25, -0.3420201433f,  -0.9396926208f)
    STEP(26, -0.1736481777f,  -0.9848077530f)
    STEP(27,  0.0f,           -1.0f)
    STEP(28,  0.1736481777f,  -0.9848077530f)
    STEP(29,  0.3420201433f,  -0.9396926208f)
    STEP(30,  0.5f,           -0.8660254038f)
    STEP(31,  0.6427876097f,  -0.7660444431f)
    STEP(32,  0.7660444431f,  -0.6427876097f)
    STEP(33,  0.8660254038f,  -0.5f)
    STEP(34,  0.9396926208f,  -0.3420201433f)
    STEP(35,  0.9848077530f,  -0.1736481777f)
}

// Block = (chunk, batch). Warp w = ring w; lanes stride the 1024 staged targets.
__global__ void __launch_bounds__(TPB)
chamfer_min_kernel(const float* __restrict__ pred,
                   const float* __restrict__ target) {
    __shared__ float4 sm[TC];   // (2tx-0.08, -2ty, -2tz, t2-0.08tx)

    const int chunk = blockIdx.x;
    const int b     = blockIdx.y;
    const int tid   = threadIdx.x;

    const float* tg = target + ((size_t)b * NTGT + (size_t)chunk * TC) * 3;
    for (int i = tid; i < TC; i += TPB) {
        float tx = tg[i * 3 + 0];
        float ty = tg[i * 3 + 1];
        float tz = tg[i * 3 + 2];
        float t2 = tx * tx + ty * ty + tz * tz;
        sm[i] = make_float4(2.0f * tx - 0.08f,
                            -2.0f * ty,
                            -2.0f * tz,
                            fmaf(-0.08f, tx, t2));
    }
    __syncthreads();

    const int ring = tid >> 5;
    const int lane = tid & 31;

    const float r  = pred[b * NRINGS + ring];
    const float py = 0.15f * (float)ring - 0.7f;
    const float Kr = r * r + py * py + 0.0016f;

    const float INF = __int_as_float(0x7f800000);
    float m[NANG];
    #pragma unroll
    for (int a = 0; a < NANG; a++) m[a] = INF;

    #pragma unroll 2
    for (int t = lane; t < TC; t += 32) {
        float4 v = sm[t];
        float Acc = fmaf(py, v.y, v.w) + Kr;
        float U   = r * v.x;
        float V   = r * v.z;
        eval36(m, U, V, Acc);
    }

    // Butterfly min across lanes per angle, then fold across chunks via
    // RED.MAX of enc(-d2) (no return value -> REDG), deterministic.
    const unsigned int pbase = (unsigned)(b * NPTS + ring * NANG);
    #pragma unroll
    for (int a = 0; a < NANG; a++) {
        float v = m[a];
        #pragma unroll
        for (int o = 16; o > 0; o >>= 1)
            v = fminf(v, __shfl_xor_sync(0xffffffffu, v, o));
        if (lane == (a & 31))
            atomicMax(&g_keys[pbase + a], enc_f32(-v));
    }
}

// Single-block deterministic finish: decode 11520 keys (46 KB), clamp, mean;
// reset keys to 0 for the next replay.
__global__ void __launch_bounds__(1024)
reduce_mean_kernel(float* __restrict__ out) {
    __shared__ float wsum[32];
    const int tid = threadIdx.x;

    uint4* keys4 = (uint4*)g_keys;
    const int n4 = (NB * NPTS) / 4;   // 2880
    const uint4 z4 = make_uint4(0u, 0u, 0u, 0u);

    float s = 0.0f;
    for (int i = tid; i < n4; i += 1024) {
        uint4 k = keys4[i];
        keys4[i] = z4;                     // restore sentinel state
        s += fmaxf(-dec_f32(k.x), 0.0f);
        s += fmaxf(-dec_f32(k.y), 0.0f);
        s += fmaxf(-dec_f32(k.z), 0.0f);
        s += fmaxf(-dec_f32(k.w), 0.0f);
    }
    #pragma unroll
    for (int o = 16; o > 0; o >>= 1) s += __shfl_down_sync(0xffffffffu, s, o);
    if ((tid & 31) == 0) wsum[tid >> 5] = s;
    __syncthreads();
    if (tid < 32) {
        float v = wsum[tid];
        #pragma unroll
        for (int o = 16; o > 0; o >>= 1) v += __shfl_down_sync(0xffffffffu, v, o);
        if (tid == 0) out[0] = v / (float)(NB * NPTS);
    }
}

extern "C" void kernel_launch(void* const* d_in, const int* in_sizes, int n_in,
                              void* d_out, int out_size) {
    const float* pred   = (const float*)d_in[0];   // (32, 10)
    const float* target = (const float*)d_in[1];   // (32, 16384, 3)
    float* out = (float*)d_out;

    dim3 grid(NCHUNK, NB);
    chamfer_min_kernel<<<grid, TPB>>>(pred, target);
    reduce_mean_kernel<<<1, 1024>>>(out);
}